// round 9
// baseline (speedup 1.0000x reference)
#include <cuda_runtime.h>
#include <cuda_fp16.h>
#include <math.h>

#define BB 32
#define TT 256
#define VV 4096
#define NROWS (BB * TT)

__device__ float g_rowS[NROWS];  // 1/Z per row
__device__ float g_ent[NROWS];   // entropy per row
__device__ float g_g[NROWS];     // final per-row scale (flag-weight / Z)
__device__ int   g_cnt[BB];      // per-batch completion counters (zero-init; net-zero per replay)

// ---------------------------------------------------------------------------
// Pass 1: per-row max/Z/entropy + q = fp16(exp(x-m)) packed uint4 into the
// first 8KB of the matching output row (aliased scratch, overwritten by the
// same thread-slot in pass 2). The LAST block of each batch (atomic counter)
// computes the flags MLP + cumprod (parallel multiply-scan) for the batch.
// ---------------------------------------------------------------------------
__global__ __launch_bounds__(256) void rowstats_kernel(const float* __restrict__ logits,
                                                       float* __restrict__ out,
                                                       const float* __restrict__ w1,
                                                       const float* __restrict__ b1,
                                                       const float* __restrict__ w2,
                                                       const float* __restrict__ b2) {
    const int row = blockIdx.x;
    const int tid = threadIdx.x;
    const int batch = row / TT;
    const float4* in = (const float4*)(logits + (size_t)row * VV);
    uint4* qrow = (uint4*)(out + (size_t)row * VV);   // 512 x 16B = 8KB

    float4 v[4];
#pragma unroll
    for (int i = 0; i < 4; i++) v[i] = __ldcs(&in[tid + 256 * i]);

    float m = -1e30f;
#pragma unroll
    for (int i = 0; i < 4; i++)
        m = fmaxf(m, fmaxf(fmaxf(v[i].x, v[i].y), fmaxf(v[i].z, v[i].w)));

    __shared__ float redm[8], redZ[8], redS[8];
    __shared__ int s_last;

#pragma unroll
    for (int o = 16; o > 0; o >>= 1)
        m = fmaxf(m, __shfl_xor_sync(0xffffffffu, m, o));
    if ((tid & 31) == 0) redm[tid >> 5] = m;
    __syncthreads();
    {
        float t2 = redm[0];
#pragma unroll
        for (int i = 1; i < 8; i++) t2 = fmaxf(t2, redm[i]);
        m = t2;
    }

    float Z = 0.f, S = 0.f;
#pragma unroll
    for (int i = 0; i < 2; i++) {
        float4 a = v[2 * i], b = v[2 * i + 1];
        float da0 = a.x - m, da1 = a.y - m, da2 = a.z - m, da3 = a.w - m;
        float db0 = b.x - m, db1 = b.y - m, db2 = b.z - m, db3 = b.w - m;
        float ea0 = __expf(da0), ea1 = __expf(da1), ea2 = __expf(da2), ea3 = __expf(da3);
        float eb0 = __expf(db0), eb1 = __expf(db1), eb2 = __expf(db2), eb3 = __expf(db3);
        Z += ea0 + ea1 + ea2 + ea3 + eb0 + eb1 + eb2 + eb3;
        S = fmaf(ea0, da0, S); S = fmaf(ea1, da1, S);
        S = fmaf(ea2, da2, S); S = fmaf(ea3, da3, S);
        S = fmaf(eb0, db0, S); S = fmaf(eb1, db1, S);
        S = fmaf(eb2, db2, S); S = fmaf(eb3, db3, S);
        __half2 h0 = __floats2half2_rn(ea0, ea1);
        __half2 h1 = __floats2half2_rn(ea2, ea3);
        __half2 h2 = __floats2half2_rn(eb0, eb1);
        __half2 h3 = __floats2half2_rn(eb2, eb3);
        uint4 u;
        u.x = *(unsigned int*)&h0;
        u.y = *(unsigned int*)&h1;
        u.z = *(unsigned int*)&h2;
        u.w = *(unsigned int*)&h3;
        qrow[tid + 256 * i] = u;   // L2-resident scratch, slots tid / tid+256
    }

#pragma unroll
    for (int o = 16; o > 0; o >>= 1) {
        Z += __shfl_xor_sync(0xffffffffu, Z, o);
        S += __shfl_xor_sync(0xffffffffu, S, o);
    }
    if ((tid & 31) == 0) { redZ[tid >> 5] = Z; redS[tid >> 5] = S; }
    __syncthreads();

    if (tid == 0) {
        float Zt = 0.f, St = 0.f;
#pragma unroll
        for (int i = 0; i < 8; i++) { Zt += redZ[i]; St += redS[i]; }
        float logZ = logf(Zt);
        g_rowS[row] = 1.0f / Zt;
        g_ent[row]  = logZ - St / Zt;
        __threadfence();                               // release stats
        int c = atomicAdd(&g_cnt[batch], 1);
        s_last = (c == TT - 1) ? 1 : 0;
    }
    __syncthreads();

    if (s_last) {
        // ---- flags for this batch, run by the last-finishing block ----
        __threadfence();                   // acquire: order RMW before our reads
        if (tid == 0) g_cnt[batch] = 0;    // reset for next graph replay

        __shared__ float sw1[128], sb1[128], sw2[128];
        __shared__ float sflag[TT];
        __shared__ float sscan[TT];

        if (tid < 128) { sw1[tid] = w1[tid]; sb1[tid] = b1[tid]; sw2[tid] = w2[tid]; }
        __syncthreads();

        float f = 1.0f;  // flags[T] = 1
        if (tid < TT - 1) {
            float e = __ldcg(&g_ent[batch * TT + tid]);
            const float entropy_max = logf((float)TT);
            float norm = 2.0f * e / entropy_max - 1.0f;
            float lin = 0.f;
#pragma unroll 8
            for (int j = 0; j < 128; j++) {
                float h = fmaxf(fmaf(norm, sw1[j], sb1[j]), 0.f);
                lin = fmaf(h, sw2[j], lin);
            }
            lin = 2.0f * lin + b2[0];
            float ns = (float)(TT - 1 - tid);
            float zarg = lin - logf(ns);
            f = 1.0f / (1.0f + expf(-zarg));
        }
        sflag[tid] = f;
        sscan[tid] = 1.0f - f;
        __syncthreads();

        // Hillis-Steele inclusive multiply-scan over (1 - f)
#pragma unroll
        for (int o = 1; o < TT; o <<= 1) {
            float prev = (tid >= o) ? sscan[tid - o] : 1.0f;
            __syncthreads();
            sscan[tid] = sscan[tid] * prev;
            __syncthreads();
        }

        float res = (tid > 0) ? sscan[tid - 1] : 1.0f;   // exclusive scan
        float invZ = __ldcg(&g_rowS[batch * TT + tid]);
        g_g[batch * TT + tid] = sflag[tid] * res * invZ;
    }
}

// ---------------------------------------------------------------------------
// Pass 2: out = half2float(q) * g_g[row]. NO BARRIER: thread tid's q lives in
// output slots {tid, tid+256}; its own stores cover {tid, tid+256, tid+512,
// tid+768}; no other thread's stores touch its q slots, and the overwrite of
// its own slots is ordered by the load->compute->store data dependence.
// Each warp streams independently -> continuous store issue.
// Reverse launch order keeps the hottest q rows in L2.
// ---------------------------------------------------------------------------
__global__ __launch_bounds__(256) void scale_kernel(float* __restrict__ out) {
    const int row = NROWS - 1 - blockIdx.x;
    const int tid = threadIdx.x;
    const float s = g_g[row];
    const uint4* qrow = (const uint4*)(out + (size_t)row * VV);
    float4* o = (float4*)(out + (size_t)row * VV);

    // issue both q loads up front (MLP=2), then convert+store as they land
    uint4 u0 = qrow[tid];
    uint4 u1 = qrow[tid + 256];

    {
        float2 f0 = __half22float2(*(__half2*)&u0.x);
        float2 f1 = __half22float2(*(__half2*)&u0.y);
        float2 f2 = __half22float2(*(__half2*)&u0.z);
        float2 f3 = __half22float2(*(__half2*)&u0.w);
        float4 r0 = make_float4(f0.x * s, f0.y * s, f1.x * s, f1.y * s);
        float4 r1 = make_float4(f2.x * s, f2.y * s, f3.x * s, f3.y * s);
        __stcs(&o[tid],       r0);   // overwrites own q slot tid (dep-ordered)
        __stcs(&o[tid + 256], r1);   // overwrites own q slot tid+256... wait: r1 belongs here
    }
    {
        float2 f0 = __half22float2(*(__half2*)&u1.x);
        float2 f1 = __half22float2(*(__half2*)&u1.y);
        float2 f2 = __half22float2(*(__half2*)&u1.z);
        float2 f3 = __half22float2(*(__half2*)&u1.w);
        float4 r2 = make_float4(f0.x * s, f0.y * s, f1.x * s, f1.y * s);
        float4 r3 = make_float4(f2.x * s, f2.y * s, f3.x * s, f3.y * s);
        __stcs(&o[tid + 512], r2);
        __stcs(&o[tid + 768], r3);
    }
}

// ---------------------------------------------------------------------------
extern "C" void kernel_launch(void* const* d_in, const int* in_sizes, int n_in,
                              void* d_out, int out_size) {
    const float* logits = (const float*)d_in[0];
    const float* w1     = (const float*)d_in[1];
    const float* b1     = (const float*)d_in[2];
    const float* w2     = (const float*)d_in[3];
    const float* b2     = (const float*)d_in[4];
    float* out          = (float*)d_out;

    rowstats_kernel<<<NROWS, 256>>>(logits, out, w1, b1, w2, b2);
    scale_kernel<<<NROWS, 256>>>(out);
}